// round 14
// baseline (speedup 1.0000x reference)
#include <cuda_runtime.h>
#include <cuda_fp16.h>
#include <cuda_bf16.h>
#include <cstdint>

// Problem constants (fixed shapes from setup_inputs)
#define L       1024
#define D_MSA   256
#define D_PAIR  128
#define D_STATE 32
#define FAN_IN  100            // 36 + 2*32
#define NMU     36
#define MU0     2.0f
#define DMU     (20.0f/35.0f)  // linspace(2,22,36) step
#define INV_DMU (35.0f/20.0f)
#define INV_SIG (36.0f/20.0f)  // 1/D_SIGMA, D_SIGMA = 20/36
#define NW      8              // rbf window; excluded terms < 2.4e-6

// Scratch (no cudaMalloc allowed)
__device__ float g_left [L * D_PAIR];
__device__ float g_right[L * D_PAIR];
__device__ float g_Cb   [L * 4];

// ---------------------------------------------------------------------------
// Kernel 1: per-residue prep. One block per i, 256 threads.
// ---------------------------------------------------------------------------
__global__ __launch_bounds__(256) void prep_kernel(
    const float* __restrict__ msa,
    const float* __restrict__ xyz,
    const float* __restrict__ state,
    const float* __restrict__ W,
    const float* __restrict__ gs, const float* __restrict__ bs,
    const float* __restrict__ gm, const float* __restrict__ bm,
    float* __restrict__ out_msa,
    float* __restrict__ out_state)
{
    const int i = blockIdx.x;
    const int t = threadIdx.x;

    __shared__ float s_part[16];
    __shared__ float s_stats[2];
    __shared__ float s_sn[D_STATE];

    // ---- msa layernorm ----
    const float x = msa[i * D_MSA + t];
    float s = x, q = x * x;
    #pragma unroll
    for (int o = 16; o; o >>= 1) {
        s += __shfl_xor_sync(0xffffffffu, s, o);
        q += __shfl_xor_sync(0xffffffffu, q, o);
    }
    const int w = t >> 5;
    if ((t & 31) == 0) { s_part[w] = s; s_part[8 + w] = q; }
    __syncthreads();
    if (t < 32) {
        float ss = (t < 8) ? s_part[t]     : 0.0f;
        float qq = (t < 8) ? s_part[8 + t] : 0.0f;
        #pragma unroll
        for (int o = 4; o; o >>= 1) {
            ss += __shfl_xor_sync(0xffffffffu, ss, o);
            qq += __shfl_xor_sync(0xffffffffu, qq, o);
        }
        if (t == 0) {
            const float m = ss * (1.0f / D_MSA);
            const float v = qq * (1.0f / D_MSA) - m * m;
            s_stats[0] = m;
            s_stats[1] = rsqrtf(v + 1e-5f);
        }
    }
    __syncthreads();
    out_msa[i * D_MSA + t] = (x - s_stats[0]) * s_stats[1] * gm[t] + bm[t];

    // ---- state layernorm (warp 0) ----
    if (t < 32) {
        const float sx = state[i * D_STATE + t];
        float ss = sx, qq = sx * sx;
        #pragma unroll
        for (int o = 16; o; o >>= 1) {
            ss += __shfl_xor_sync(0xffffffffu, ss, o);
            qq += __shfl_xor_sync(0xffffffffu, qq, o);
        }
        const float m = ss * (1.0f / D_STATE);
        const float v = qq * (1.0f / D_STATE) - m * m;
        const float rstd = rsqrtf(v + 1e-5f);
        const float sn = (sx - m) * rstd * gs[t] + bs[t];
        s_sn[t] = sn;
        out_state[i * D_STATE + t] = sn;
    }

    // ---- Cb geometry ----
    if (t == 64) {
        const float* p = xyz + i * 9;
        const float Nx = p[0], Ny = p[1], Nz = p[2];
        const float Ax = p[3], Ay = p[4], Az = p[5];
        const float Cx = p[6], Cy = p[7], Cz = p[8];
        const float bx = Ax - Nx, by = Ay - Ny, bz = Az - Nz;
        const float cx = Cx - Ax, cy = Cy - Ay, cz = Cz - Az;
        const float ax = by * cz - bz * cy;
        const float ay = bz * cx - bx * cz;
        const float az = bx * cy - by * cx;
        g_Cb[i * 4 + 0] = -0.58273431f * ax + 0.56802827f * bx - 0.54067466f * cx + Ax;
        g_Cb[i * 4 + 1] = -0.58273431f * ay + 0.56802827f * by - 0.54067466f * cy + Ay;
        g_Cb[i * 4 + 2] = -0.58273431f * az + 0.56802827f * bz - 0.54067466f * cz + Az;
        g_Cb[i * 4 + 3] = 0.0f;
    }
    __syncthreads();

    // ---- left/right projections: W is [128][100] row-major ----
    if (t < 128) {
        const float* wr = W + t * FAN_IN + NMU;           // W_l row
        float acc = 0.0f;
        #pragma unroll
        for (int k = 0; k < D_STATE; ++k) acc += s_sn[k] * wr[k];
        g_left[i * D_PAIR + t] = acc;
    } else {
        const int p = t - 128;
        const float* wr = W + p * FAN_IN + NMU + D_STATE; // W_r row
        float acc = 0.0f;
        #pragma unroll
        for (int k = 0; k < D_STATE; ++k) acc += s_sn[k] * wr[k];
        g_right[i * D_PAIR + p] = acc;
    }
}

// ---------------------------------------------------------------------------
// Kernel 2: pair_out[i,j,:]. grid = (16, 1024), 256 threads = 8 warps.
// Each warp iterates over JW=8 j's, 2 at a time: lanes 0-15 handle j0,
// lanes 16-31 handle j1. A lane owns 8 channels: [ca..ca+3] and [ca+64..+67].
// W_d held in shared as fp16 (LDS.64 fetch), accumulated in fp32.
// ---------------------------------------------------------------------------
#define JW 8

__global__ __launch_bounds__(256, 3) void pair_kernel(
    const float* __restrict__ pair,
    const float* __restrict__ W,
    const float* __restrict__ b_proj,
    const float* __restrict__ gp_g, const float* __restrict__ bp_g,
    float* __restrict__ out_pair)
{
    __shared__ __half s_wd[NMU * D_PAIR];   // W_d transposed [k][p], fp16, 9 KB
    __shared__ float  s_base[D_PAIR];       // left[i] + b_proj

    const int i = blockIdx.y;
    const int t = threadIdx.x;

    for (int idx = t; idx < NMU * D_PAIR; idx += 256) {
        const int p = idx & (D_PAIR - 1);
        const int k = idx >> 7;
        s_wd[idx] = __float2half(W[p * FAN_IN + k]);
    }
    if (t < D_PAIR) s_base[t] = g_left[i * D_PAIR + t] + b_proj[t];
    __syncthreads();

    const int lane = t & 31;
    const int warp = t >> 5;
    const int hf   = lane >> 4;      // which j of the pair this lane serves
    const int l16  = lane & 15;
    const int ca   = l16 * 4;        // channels ca..ca+3 and ca+64..ca+67

    // per-channel constants (registers)
    const float4 ga = *(const float4*)(gp_g + ca);
    const float4 gb = *(const float4*)(gp_g + ca + 64);
    const float4 bpa = *(const float4*)(bp_g + ca);
    const float4 bpb = *(const float4*)(bp_g + ca + 64);
    const float4 basea = *(const float4*)(s_base + ca);
    const float4 baseb = *(const float4*)(s_base + ca + 64);
    const float4 cbi = *(const float4*)(g_Cb + i * 4);

    const int jbase = blockIdx.x * (8 * JW) + warp * JW;

    for (int jj = 0; jj < JW; jj += 2) {
        const int j = jbase + jj + hf;
        const size_t row = ((size_t)i * L + j) * D_PAIR;

        // pair row slice (each LDG.128 covers 256B of each of the two rows)
        const float4 pa = *(const float4*)(pair + row + ca);
        const float4 pb = *(const float4*)(pair + row + ca + 64);

        float s = (pa.x + pa.y) + (pa.z + pa.w) + (pb.x + pb.y) + (pb.z + pb.w);
        float q = pa.x * pa.x + pa.y * pa.y + pa.z * pa.z + pa.w * pa.w
                + pb.x * pb.x + pb.y * pb.y + pb.z * pb.z + pb.w * pb.w;
        #pragma unroll
        for (int o = 8; o; o >>= 1) {     // 16-lane butterfly, stays in half
            s += __shfl_xor_sync(0xffffffffu, s, o);
            q += __shfl_xor_sync(0xffffffffu, q, o);
        }
        const float mean = s * (1.0f / D_PAIR);
        const float var  = q * (1.0f / D_PAIR) - mean * mean;
        const float rstd = rsqrtf(var + 1e-5f);

        // distance + windowed rbf (one j per half-warp)
        const float4 cbj = *(const float4*)(g_Cb + j * 4);
        const float dx = cbi.x - cbj.x, dy = cbi.y - cbj.y, dz = cbi.z - cbj.z;
        const float D = sqrtf(fmaxf(dx * dx + dy * dy + dz * dz, 1e-12f));
        int k0 = (int)floorf((D - MU0) * INV_DMU + 0.5f) - (NW / 2);
        k0 = max(0, min(NMU - NW, k0));
        float myr = 0.0f;
        if (l16 < NW) {
            const float mu = MU0 + (float)(k0 + l16) * DMU;
            const float xx = (D - mu) * INV_SIG;
            myr = __expf(-xx * xx);
        }

        // acc = left[i] + b_proj + right[j] + sum_k r_k * W_d[:,k]
        const float4 ra = *(const float4*)(g_right + (size_t)j * D_PAIR + ca);
        const float4 rb = *(const float4*)(g_right + (size_t)j * D_PAIR + ca + 64);
        float4 acc_a, acc_b;
        acc_a.x = basea.x + ra.x; acc_a.y = basea.y + ra.y;
        acc_a.z = basea.z + ra.z; acc_a.w = basea.w + ra.w;
        acc_b.x = baseb.x + rb.x; acc_b.y = baseb.y + rb.y;
        acc_b.z = baseb.z + rb.z; acc_b.w = baseb.w + rb.w;

        const __half* wbase = s_wd + k0 * D_PAIR + ca;
        #pragma unroll
        for (int k = 0; k < NW; ++k) {
            const float r = __shfl_sync(0xffffffffu, myr, k, 16); // per-half source
            const uint2 wa = *(const uint2*)(wbase + k * D_PAIR);
            const uint2 wb = *(const uint2*)(wbase + k * D_PAIR + 64);
            const float2 wa0 = __half22float2(*(const __half2*)&wa.x);
            const float2 wa1 = __half22float2(*(const __half2*)&wa.y);
            const float2 wb0 = __half22float2(*(const __half2*)&wb.x);
            const float2 wb1 = __half22float2(*(const __half2*)&wb.y);
            acc_a.x += r * wa0.x; acc_a.y += r * wa0.y;
            acc_a.z += r * wa1.x; acc_a.w += r * wa1.y;
            acc_b.x += r * wb0.x; acc_b.y += r * wb0.y;
            acc_b.z += r * wb1.x; acc_b.w += r * wb1.y;
        }

        // + layernorm(pair)
        float4 oa, ob;
        oa.x = acc_a.x + (pa.x - mean) * rstd * ga.x + bpa.x;
        oa.y = acc_a.y + (pa.y - mean) * rstd * ga.y + bpa.y;
        oa.z = acc_a.z + (pa.z - mean) * rstd * ga.z + bpa.z;
        oa.w = acc_a.w + (pa.w - mean) * rstd * ga.w + bpa.w;
        ob.x = acc_b.x + (pb.x - mean) * rstd * gb.x + bpb.x;
        ob.y = acc_b.y + (pb.y - mean) * rstd * gb.y + bpb.y;
        ob.z = acc_b.z + (pb.z - mean) * rstd * gb.z + bpb.z;
        ob.w = acc_b.w + (pb.w - mean) * rstd * gb.w + bpb.w;
        *(float4*)(out_pair + row + ca)      = oa;
        *(float4*)(out_pair + row + ca + 64) = ob;
    }
}

// ---------------------------------------------------------------------------
// Launch. Inputs (metadata order):
//  0 seq(i32,unused) 1 msa 2 pair 3 xyz 4 state 5 W 6 b_proj
//  7 g_state 8 b_state 9 g_pair 10 b_pair 11 g_msa 12 b_msa
// Output: concat(msa_out, pair_out, state_n) f32
// ---------------------------------------------------------------------------
extern "C" void kernel_launch(void* const* d_in, const int* in_sizes, int n_in,
                              void* d_out, int out_size)
{
    (void)in_sizes; (void)n_in; (void)out_size;
    const float* msa    = (const float*)d_in[1];
    const float* pair   = (const float*)d_in[2];
    const float* xyz    = (const float*)d_in[3];
    const float* state  = (const float*)d_in[4];
    const float* W      = (const float*)d_in[5];
    const float* b_proj = (const float*)d_in[6];
    const float* gs     = (const float*)d_in[7];
    const float* bs     = (const float*)d_in[8];
    const float* gp     = (const float*)d_in[9];
    const float* bp     = (const float*)d_in[10];
    const float* gm     = (const float*)d_in[11];
    const float* bm     = (const float*)d_in[12];

    float* out       = (float*)d_out;
    float* out_msa   = out;
    float* out_pair  = out + (size_t)L * D_MSA;
    float* out_state = out_pair + (size_t)L * L * D_PAIR;

    prep_kernel<<<L, 256>>>(msa, xyz, state, W, gs, bs, gm, bm, out_msa, out_state);

    dim3 grid(L / (8 * JW), L);
    pair_kernel<<<grid, 256>>>(pair, W, b_proj, gp, bp, out_pair);
}

// round 15
// speedup vs baseline: 1.0598x; 1.0598x over previous
#include <cuda_runtime.h>
#include <cuda_fp16.h>
#include <cuda_bf16.h>
#include <cstdint>

// Problem constants (fixed shapes from setup_inputs)
#define L       1024
#define D_MSA   256
#define D_PAIR  128
#define D_STATE 32
#define FAN_IN  100            // 36 + 2*32
#define NMU     36
#define MU0     2.0f
#define DMU     (20.0f/35.0f)  // linspace(2,22,36) step
#define INV_DMU (35.0f/20.0f)
#define INV_SIG (36.0f/20.0f)  // 1/D_SIGMA, D_SIGMA = 20/36
#define NW      8              // rbf window; excluded terms < 2.4e-6

// Scratch (no cudaMalloc allowed)
__device__ float g_left [L * D_PAIR];
__device__ float g_right[L * D_PAIR];
__device__ float g_Cb   [L * 4];

// ---------------------------------------------------------------------------
// Kernel 1: per-residue prep. One block per i, 256 threads.
// ---------------------------------------------------------------------------
__global__ __launch_bounds__(256) void prep_kernel(
    const float* __restrict__ msa,
    const float* __restrict__ xyz,
    const float* __restrict__ state,
    const float* __restrict__ W,
    const float* __restrict__ gs, const float* __restrict__ bs,
    const float* __restrict__ gm, const float* __restrict__ bm,
    float* __restrict__ out_msa,
    float* __restrict__ out_state)
{
    const int i = blockIdx.x;
    const int t = threadIdx.x;

    __shared__ float s_part[16];
    __shared__ float s_stats[2];
    __shared__ float s_sn[D_STATE];

    // ---- msa layernorm ----
    const float x = msa[i * D_MSA + t];
    float s = x, q = x * x;
    #pragma unroll
    for (int o = 16; o; o >>= 1) {
        s += __shfl_xor_sync(0xffffffffu, s, o);
        q += __shfl_xor_sync(0xffffffffu, q, o);
    }
    const int w = t >> 5;
    if ((t & 31) == 0) { s_part[w] = s; s_part[8 + w] = q; }
    __syncthreads();
    if (t < 32) {
        float ss = (t < 8) ? s_part[t]     : 0.0f;
        float qq = (t < 8) ? s_part[8 + t] : 0.0f;
        #pragma unroll
        for (int o = 4; o; o >>= 1) {
            ss += __shfl_xor_sync(0xffffffffu, ss, o);
            qq += __shfl_xor_sync(0xffffffffu, qq, o);
        }
        if (t == 0) {
            const float m = ss * (1.0f / D_MSA);
            const float v = qq * (1.0f / D_MSA) - m * m;
            s_stats[0] = m;
            s_stats[1] = rsqrtf(v + 1e-5f);
        }
    }
    __syncthreads();
    out_msa[i * D_MSA + t] = (x - s_stats[0]) * s_stats[1] * gm[t] + bm[t];

    // ---- state layernorm (warp 0) ----
    if (t < 32) {
        const float sx = state[i * D_STATE + t];
        float ss = sx, qq = sx * sx;
        #pragma unroll
        for (int o = 16; o; o >>= 1) {
            ss += __shfl_xor_sync(0xffffffffu, ss, o);
            qq += __shfl_xor_sync(0xffffffffu, qq, o);
        }
        const float m = ss * (1.0f / D_STATE);
        const float v = qq * (1.0f / D_STATE) - m * m;
        const float rstd = rsqrtf(v + 1e-5f);
        const float sn = (sx - m) * rstd * gs[t] + bs[t];
        s_sn[t] = sn;
        out_state[i * D_STATE + t] = sn;
    }

    // ---- Cb geometry ----
    if (t == 64) {
        const float* p = xyz + i * 9;
        const float Nx = p[0], Ny = p[1], Nz = p[2];
        const float Ax = p[3], Ay = p[4], Az = p[5];
        const float Cx = p[6], Cy = p[7], Cz = p[8];
        const float bx = Ax - Nx, by = Ay - Ny, bz = Az - Nz;
        const float cx = Cx - Ax, cy = Cy - Ay, cz = Cz - Az;
        const float ax = by * cz - bz * cy;
        const float ay = bz * cx - bx * cz;
        const float az = bx * cy - by * cx;
        g_Cb[i * 4 + 0] = -0.58273431f * ax + 0.56802827f * bx - 0.54067466f * cx + Ax;
        g_Cb[i * 4 + 1] = -0.58273431f * ay + 0.56802827f * by - 0.54067466f * cy + Ay;
        g_Cb[i * 4 + 2] = -0.58273431f * az + 0.56802827f * bz - 0.54067466f * cz + Az;
        g_Cb[i * 4 + 3] = 0.0f;
    }
    __syncthreads();

    // ---- left/right projections: W is [128][100] row-major ----
    if (t < 128) {
        const float* wr = W + t * FAN_IN + NMU;           // W_l row
        float acc = 0.0f;
        #pragma unroll
        for (int k = 0; k < D_STATE; ++k) acc += s_sn[k] * wr[k];
        g_left[i * D_PAIR + t] = acc;
    } else {
        const int p = t - 128;
        const float* wr = W + p * FAN_IN + NMU + D_STATE; // W_r row
        float acc = 0.0f;
        #pragma unroll
        for (int k = 0; k < D_STATE; ++k) acc += s_sn[k] * wr[k];
        g_right[i * D_PAIR + p] = acc;
    }
}

// ---------------------------------------------------------------------------
// Kernel 2: pair_out[i,j,:]. grid = (16, 1024), 256 threads = 8 warps.
// Each warp iterates over JW=8 j's, 2 at a time: lanes 0-15 handle j0,
// lanes 16-31 handle j1. A lane owns 8 channels: [ca..ca+3] and [ca+64..+67].
// W_d in shared as fp16, repacked so each lane's 8 channels are one LDS.128.
// ---------------------------------------------------------------------------
#define JW 8

__global__ __launch_bounds__(256, 4) void pair_kernel(
    const float* __restrict__ pair,
    const float* __restrict__ W,
    const float* __restrict__ b_proj,
    const float* __restrict__ gp_g, const float* __restrict__ bp_g,
    float* __restrict__ out_pair)
{
    // s_wd[k][l16*8 + s]: s=0..3 -> channel l16*4+s ; s=4..7 -> channel l16*4+64+(s-4)
    __shared__ __half s_wd[NMU * D_PAIR];   // 9 KB
    __shared__ float  s_base[D_PAIR];       // left[i] + b_proj + b_pair

    const int i = blockIdx.y;
    const int t = threadIdx.x;

    for (int idx = t; idx < NMU * D_PAIR; idx += 256) {
        const int k   = idx >> 7;
        const int r   = idx & 127;
        const int g16 = r >> 3;
        const int sub = r & 7;
        const int p   = g16 * 4 + (sub & 3) + ((sub & 4) << 4);  // +64 if sub>=4
        s_wd[idx] = __float2half(W[p * FAN_IN + k]);
    }
    if (t < D_PAIR) s_base[t] = g_left[i * D_PAIR + t] + b_proj[t] + bp_g[t];
    __syncthreads();

    const int lane = t & 31;
    const int warp = t >> 5;
    const int hf   = lane >> 4;      // which j of the pair this lane serves
    const int l16  = lane & 15;
    const int ca   = l16 * 4;        // channels ca..ca+3 and ca+64..ca+67

    // per-channel constants (registers)
    const float4 ga = *(const float4*)(gp_g + ca);
    const float4 gb = *(const float4*)(gp_g + ca + 64);
    const float4 basea = *(const float4*)(s_base + ca);
    const float4 baseb = *(const float4*)(s_base + ca + 64);
    const float4 cbi = *(const float4*)(g_Cb + i * 4);

    const int jbase = blockIdx.x * (8 * JW) + warp * JW;

    for (int jj = 0; jj < JW; jj += 2) {
        const int j = jbase + jj + hf;
        const size_t row = ((size_t)i * L + j) * D_PAIR;

        // pair row slice
        const float4 pa = *(const float4*)(pair + row + ca);
        const float4 pb = *(const float4*)(pair + row + ca + 64);

        float s = (pa.x + pa.y) + (pa.z + pa.w) + (pb.x + pb.y) + (pb.z + pb.w);
        float q = pa.x * pa.x + pa.y * pa.y + pa.z * pa.z + pa.w * pa.w
                + pb.x * pb.x + pb.y * pb.y + pb.z * pb.z + pb.w * pb.w;
        #pragma unroll
        for (int o = 8; o; o >>= 1) {     // 16-lane butterfly, stays in half
            s += __shfl_xor_sync(0xffffffffu, s, o);
            q += __shfl_xor_sync(0xffffffffu, q, o);
        }
        const float mean = s * (1.0f / D_PAIR);
        const float var  = q * (1.0f / D_PAIR) - mean * mean;
        const float rstd = rsqrtf(var + 1e-5f);

        // distance + windowed rbf (one j per half-warp)
        const float4 cbj = *(const float4*)(g_Cb + j * 4);
        const float dx = cbi.x - cbj.x, dy = cbi.y - cbj.y, dz = cbi.z - cbj.z;
        const float D = sqrtf(fmaxf(dx * dx + dy * dy + dz * dz, 1e-12f));
        int k0 = (int)floorf((D - MU0) * INV_DMU + 0.5f) - (NW / 2);
        k0 = max(0, min(NMU - NW, k0));
        float myr = 0.0f;
        if (l16 < NW) {
            const float mu = MU0 + (float)(k0 + l16) * DMU;
            const float xx = (D - mu) * INV_SIG;
            myr = __expf(-xx * xx);
        }

        // acc = base + right[j] + sum_k r_k * W_d[:,k]
        const float4 ra = *(const float4*)(g_right + (size_t)j * D_PAIR + ca);
        const float4 rb = *(const float4*)(g_right + (size_t)j * D_PAIR + ca + 64);
        float4 acc_a, acc_b;
        acc_a.x = basea.x + ra.x; acc_a.y = basea.y + ra.y;
        acc_a.z = basea.z + ra.z; acc_a.w = basea.w + ra.w;
        acc_b.x = baseb.x + rb.x; acc_b.y = baseb.y + rb.y;
        acc_b.z = baseb.z + rb.z; acc_b.w = baseb.w + rb.w;

        const __half* wbase = s_wd + k0 * D_PAIR + l16 * 8;
        #pragma unroll
        for (int k = 0; k < NW; ++k) {
            const float r = __shfl_sync(0xffffffffu, myr, k, 16); // per-half source
            const uint4 wv = *(const uint4*)(wbase + k * D_PAIR); // 8 halfs, one LDS.128
            const float2 wa0 = __half22float2(*(const __half2*)&wv.x);
            const float2 wa1 = __half22float2(*(const __half2*)&wv.y);
            const float2 wb0 = __half22float2(*(const __half2*)&wv.z);
            const float2 wb1 = __half22float2(*(const __half2*)&wv.w);
            acc_a.x += r * wa0.x; acc_a.y += r * wa0.y;
            acc_a.z += r * wa1.x; acc_a.w += r * wa1.y;
            acc_b.x += r * wb0.x; acc_b.y += r * wb0.y;
            acc_b.z += r * wb1.x; acc_b.w += r * wb1.y;
        }

        // + layernorm(pair)  (b_pair already folded into base)
        float4 oa, ob;
        oa.x = acc_a.x + (pa.x - mean) * rstd * ga.x;
        oa.y = acc_a.y + (pa.y - mean) * rstd * ga.y;
        oa.z = acc_a.z + (pa.z - mean) * rstd * ga.z;
        oa.w = acc_a.w + (pa.w - mean) * rstd * ga.w;
        ob.x = acc_b.x + (pb.x - mean) * rstd * gb.x;
        ob.y = acc_b.y + (pb.y - mean) * rstd * gb.y;
        ob.z = acc_b.z + (pb.z - mean) * rstd * gb.z;
        ob.w = acc_b.w + (pb.w - mean) * rstd * gb.w;
        *(float4*)(out_pair + row + ca)      = oa;
        *(float4*)(out_pair + row + ca + 64) = ob;
    }
}

// ---------------------------------------------------------------------------
// Launch. Inputs (metadata order):
//  0 seq(i32,unused) 1 msa 2 pair 3 xyz 4 state 5 W 6 b_proj
//  7 g_state 8 b_state 9 g_pair 10 b_pair 11 g_msa 12 b_msa
// Output: concat(msa_out, pair_out, state_n) f32
// ---------------------------------------------------------------------------
extern "C" void kernel_launch(void* const* d_in, const int* in_sizes, int n_in,
                              void* d_out, int out_size)
{
    (void)in_sizes; (void)n_in; (void)out_size;
    const float* msa    = (const float*)d_in[1];
    const float* pair   = (const float*)d_in[2];
    const float* xyz    = (const float*)d_in[3];
    const float* state  = (const float*)d_in[4];
    const float* W      = (const float*)d_in[5];
    const float* b_proj = (const float*)d_in[6];
    const float* gs     = (const float*)d_in[7];
    const float* bs     = (const float*)d_in[8];
    const float* gp     = (const float*)d_in[9];
    const float* bp     = (const float*)d_in[10];
    const float* gm     = (const float*)d_in[11];
    const float* bm     = (const float*)d_in[12];

    float* out       = (float*)d_out;
    float* out_msa   = out;
    float* out_pair  = out + (size_t)L * D_MSA;
    float* out_state = out_pair + (size_t)L * L * D_PAIR;

    prep_kernel<<<L, 256>>>(msa, xyz, state, W, gs, bs, gm, bm, out_msa, out_state);

    dim3 grid(L / (8 * JW), L);
    pair_kernel<<<grid, 256>>>(pair, W, b_proj, gp, bp, out_pair);
}

// round 16
// speedup vs baseline: 1.1060x; 1.0436x over previous
#include <cuda_runtime.h>
#include <cuda_fp16.h>
#include <cuda_bf16.h>
#include <cstdint>

// Problem constants (fixed shapes from setup_inputs)
#define L       1024
#define D_MSA   256
#define D_PAIR  128
#define D_STATE 32
#define FAN_IN  100            // 36 + 2*32
#define NMU     36
#define MU0     2.0f
#define DMU     (20.0f/35.0f)  // linspace(2,22,36) step
#define INV_DMU (35.0f/20.0f)
#define INV_SIG (36.0f/20.0f)  // 1/D_SIGMA, D_SIGMA = 20/36
#define NW      8              // rbf window; excluded terms < 2.4e-6

// Scratch (no cudaMalloc allowed)
__device__ float g_left [L * D_PAIR];
__device__ float g_right[L * D_PAIR];
__device__ float g_Cb   [L * 4];

// ---------------------------------------------------------------------------
// Kernel 1: per-residue prep. One block per i, 256 threads.
// ---------------------------------------------------------------------------
__global__ __launch_bounds__(256) void prep_kernel(
    const float* __restrict__ msa,
    const float* __restrict__ xyz,
    const float* __restrict__ state,
    const float* __restrict__ W,
    const float* __restrict__ gs, const float* __restrict__ bs,
    const float* __restrict__ gm, const float* __restrict__ bm,
    float* __restrict__ out_msa,
    float* __restrict__ out_state)
{
    const int i = blockIdx.x;
    const int t = threadIdx.x;

    __shared__ float s_part[16];
    __shared__ float s_stats[2];
    __shared__ float s_sn[D_STATE];

    // ---- msa layernorm ----
    const float x = msa[i * D_MSA + t];
    float s = x, q = x * x;
    #pragma unroll
    for (int o = 16; o; o >>= 1) {
        s += __shfl_xor_sync(0xffffffffu, s, o);
        q += __shfl_xor_sync(0xffffffffu, q, o);
    }
    const int w = t >> 5;
    if ((t & 31) == 0) { s_part[w] = s; s_part[8 + w] = q; }
    __syncthreads();
    if (t < 32) {
        float ss = (t < 8) ? s_part[t]     : 0.0f;
        float qq = (t < 8) ? s_part[8 + t] : 0.0f;
        #pragma unroll
        for (int o = 4; o; o >>= 1) {
            ss += __shfl_xor_sync(0xffffffffu, ss, o);
            qq += __shfl_xor_sync(0xffffffffu, qq, o);
        }
        if (t == 0) {
            const float m = ss * (1.0f / D_MSA);
            const float v = qq * (1.0f / D_MSA) - m * m;
            s_stats[0] = m;
            s_stats[1] = rsqrtf(v + 1e-5f);
        }
    }
    __syncthreads();
    out_msa[i * D_MSA + t] = (x - s_stats[0]) * s_stats[1] * gm[t] + bm[t];

    // ---- state layernorm (warp 0) ----
    if (t < 32) {
        const float sx = state[i * D_STATE + t];
        float ss = sx, qq = sx * sx;
        #pragma unroll
        for (int o = 16; o; o >>= 1) {
            ss += __shfl_xor_sync(0xffffffffu, ss, o);
            qq += __shfl_xor_sync(0xffffffffu, qq, o);
        }
        const float m = ss * (1.0f / D_STATE);
        const float v = qq * (1.0f / D_STATE) - m * m;
        const float rstd = rsqrtf(v + 1e-5f);
        const float sn = (sx - m) * rstd * gs[t] + bs[t];
        s_sn[t] = sn;
        out_state[i * D_STATE + t] = sn;
    }

    // ---- Cb geometry ----
    if (t == 64) {
        const float* p = xyz + i * 9;
        const float Nx = p[0], Ny = p[1], Nz = p[2];
        const float Ax = p[3], Ay = p[4], Az = p[5];
        const float Cx = p[6], Cy = p[7], Cz = p[8];
        const float bx = Ax - Nx, by = Ay - Ny, bz = Az - Nz;
        const float cx = Cx - Ax, cy = Cy - Ay, cz = Cz - Az;
        const float ax = by * cz - bz * cy;
        const float ay = bz * cx - bx * cz;
        const float az = bx * cy - by * cx;
        g_Cb[i * 4 + 0] = -0.58273431f * ax + 0.56802827f * bx - 0.54067466f * cx + Ax;
        g_Cb[i * 4 + 1] = -0.58273431f * ay + 0.56802827f * by - 0.54067466f * cy + Ay;
        g_Cb[i * 4 + 2] = -0.58273431f * az + 0.56802827f * bz - 0.54067466f * cz + Az;
        g_Cb[i * 4 + 3] = 0.0f;
    }
    __syncthreads();

    // ---- left/right projections: W is [128][100] row-major ----
    if (t < 128) {
        const float* wr = W + t * FAN_IN + NMU;           // W_l row
        float acc = 0.0f;
        #pragma unroll
        for (int k = 0; k < D_STATE; ++k) acc += s_sn[k] * wr[k];
        g_left[i * D_PAIR + t] = acc;
    } else {
        const int p = t - 128;
        const float* wr = W + p * FAN_IN + NMU + D_STATE; // W_r row
        float acc = 0.0f;
        #pragma unroll
        for (int k = 0; k < D_STATE; ++k) acc += s_sn[k] * wr[k];
        g_right[i * D_PAIR + p] = acc;
    }
}

// ---------------------------------------------------------------------------
// Kernel 2: pair_out[i,j,:]. grid = (16, 1024), 256 threads = 8 warps.
// Each warp iterates over JW=8 j's, 2 at a time: lanes 0-15 handle j0,
// lanes 16-31 handle j1. A lane owns 8 channels: [ca..ca+3] and [ca+64..+67].
// W_d in shared as fp16, repacked so each lane's 8 channels are one LDS.128.
// ---------------------------------------------------------------------------
#define JW 8

__global__ __launch_bounds__(256, 4) void pair_kernel(
    const float* __restrict__ pair,
    const float* __restrict__ W,
    const float* __restrict__ b_proj,
    const float* __restrict__ gp_g, const float* __restrict__ bp_g,
    float* __restrict__ out_pair)
{
    // s_wd[k][l16*8 + s]: s=0..3 -> channel l16*4+s ; s=4..7 -> channel l16*4+64+(s-4)
    __shared__ __half s_wd[NMU * D_PAIR];   // 9 KB
    __shared__ float  s_base[D_PAIR];       // left[i] + b_proj + b_pair

    const int i = blockIdx.y;
    const int t = threadIdx.x;

    for (int idx = t; idx < NMU * D_PAIR; idx += 256) {
        const int k   = idx >> 7;
        const int r   = idx & 127;
        const int g16 = r >> 3;
        const int sub = r & 7;
        const int p   = g16 * 4 + (sub & 3) + ((sub & 4) << 4);  // +64 if sub>=4
        s_wd[idx] = __float2half(W[p * FAN_IN + k]);
    }
    if (t < D_PAIR) s_base[t] = g_left[i * D_PAIR + t] + b_proj[t] + bp_g[t];
    __syncthreads();

    const int lane = t & 31;
    const int warp = t >> 5;
    const int hf   = lane >> 4;      // which j of the pair this lane serves
    const int l16  = lane & 15;
    const int ca   = l16 * 4;        // channels ca..ca+3 and ca+64..ca+67

    // per-channel constants (registers)
    const float4 ga = *(const float4*)(gp_g + ca);
    const float4 gb = *(const float4*)(gp_g + ca + 64);
    const float4 basea = *(const float4*)(s_base + ca);
    const float4 baseb = *(const float4*)(s_base + ca + 64);
    const float4 cbi = *(const float4*)(g_Cb + i * 4);

    const int jbase = blockIdx.x * (8 * JW) + warp * JW;

    for (int jj = 0; jj < JW; jj += 2) {
        const int j = jbase + jj + hf;
        const size_t row = ((size_t)i * L + j) * D_PAIR;

        // pair row slice
        const float4 pa = *(const float4*)(pair + row + ca);
        const float4 pb = *(const float4*)(pair + row + ca + 64);

        float s = (pa.x + pa.y) + (pa.z + pa.w) + (pb.x + pb.y) + (pb.z + pb.w);
        float q = pa.x * pa.x + pa.y * pa.y + pa.z * pa.z + pa.w * pa.w
                + pb.x * pb.x + pb.y * pb.y + pb.z * pb.z + pb.w * pb.w;
        #pragma unroll
        for (int o = 8; o; o >>= 1) {     // 16-lane butterfly, stays in half
            s += __shfl_xor_sync(0xffffffffu, s, o);
            q += __shfl_xor_sync(0xffffffffu, q, o);
        }
        const float mean = s * (1.0f / D_PAIR);
        const float var  = q * (1.0f / D_PAIR) - mean * mean;
        const float rstd = rsqrtf(var + 1e-5f);

        // distance + windowed rbf (one j per half-warp)
        const float4 cbj = *(const float4*)(g_Cb + j * 4);
        const float dx = cbi.x - cbj.x, dy = cbi.y - cbj.y, dz = cbi.z - cbj.z;
        const float D = sqrtf(fmaxf(dx * dx + dy * dy + dz * dz, 1e-12f));
        int k0 = (int)floorf((D - MU0) * INV_DMU + 0.5f) - (NW / 2);
        k0 = max(0, min(NMU - NW, k0));
        float myr = 0.0f;
        if (l16 < NW) {
            const float mu = MU0 + (float)(k0 + l16) * DMU;
            const float xx = (D - mu) * INV_SIG;
            myr = __expf(-xx * xx);
        }

        // acc = base + right[j] + sum_k r_k * W_d[:,k]
        const float4 ra = *(const float4*)(g_right + (size_t)j * D_PAIR + ca);
        const float4 rb = *(const float4*)(g_right + (size_t)j * D_PAIR + ca + 64);
        float4 acc_a, acc_b;
        acc_a.x = basea.x + ra.x; acc_a.y = basea.y + ra.y;
        acc_a.z = basea.z + ra.z; acc_a.w = basea.w + ra.w;
        acc_b.x = baseb.x + rb.x; acc_b.y = baseb.y + rb.y;
        acc_b.z = baseb.z + rb.z; acc_b.w = baseb.w + rb.w;

        const __half* wbase = s_wd + k0 * D_PAIR + l16 * 8;
        #pragma unroll
        for (int k = 0; k < NW; ++k) {
            const float r = __shfl_sync(0xffffffffu, myr, k, 16); // per-half source
            const uint4 wv = *(const uint4*)(wbase + k * D_PAIR); // 8 halfs, one LDS.128
            const float2 wa0 = __half22float2(*(const __half2*)&wv.x);
            const float2 wa1 = __half22float2(*(const __half2*)&wv.y);
            const float2 wb0 = __half22float2(*(const __half2*)&wv.z);
            const float2 wb1 = __half22float2(*(const __half2*)&wv.w);
            acc_a.x += r * wa0.x; acc_a.y += r * wa0.y;
            acc_a.z += r * wa1.x; acc_a.w += r * wa1.y;
            acc_b.x += r * wb0.x; acc_b.y += r * wb0.y;
            acc_b.z += r * wb1.x; acc_b.w += r * wb1.y;
        }

        // + layernorm(pair)  (b_pair already folded into base)
        float4 oa, ob;
        oa.x = acc_a.x + (pa.x - mean) * rstd * ga.x;
        oa.y = acc_a.y + (pa.y - mean) * rstd * ga.y;
        oa.z = acc_a.z + (pa.z - mean) * rstd * ga.z;
        oa.w = acc_a.w + (pa.w - mean) * rstd * ga.w;
        ob.x = acc_b.x + (pb.x - mean) * rstd * gb.x;
        ob.y = acc_b.y + (pb.y - mean) * rstd * gb.y;
        ob.z = acc_b.z + (pb.z - mean) * rstd * gb.z;
        ob.w = acc_b.w + (pb.w - mean) * rstd * gb.w;
        *(float4*)(out_pair + row + ca)      = oa;
        *(float4*)(out_pair + row + ca + 64) = ob;
    }
}

// ---------------------------------------------------------------------------
// Launch. Inputs (metadata order):
//  0 seq(i32,unused) 1 msa 2 pair 3 xyz 4 state 5 W 6 b_proj
//  7 g_state 8 b_state 9 g_pair 10 b_pair 11 g_msa 12 b_msa
// Output: concat(msa_out, pair_out, state_n) f32
// ---------------------------------------------------------------------------
extern "C" void kernel_launch(void* const* d_in, const int* in_sizes, int n_in,
                              void* d_out, int out_size)
{
    (void)in_sizes; (void)n_in; (void)out_size;
    const float* msa    = (const float*)d_in[1];
    const float* pair   = (const float*)d_in[2];
    const float* xyz    = (const float*)d_in[3];
    const float* state  = (const float*)d_in[4];
    const float* W      = (const float*)d_in[5];
    const float* b_proj = (const float*)d_in[6];
    const float* gs     = (const float*)d_in[7];
    const float* bs     = (const float*)d_in[8];
    const float* gp     = (const float*)d_in[9];
    const float* bp     = (const float*)d_in[10];
    const float* gm     = (const float*)d_in[11];
    const float* bm     = (const float*)d_in[12];

    float* out       = (float*)d_out;
    float* out_msa   = out;
    float* out_pair  = out + (size_t)L * D_MSA;
    float* out_state = out_pair + (size_t)L * L * D_PAIR;

    prep_kernel<<<L, 256>>>(msa, xyz, state, W, gs, bs, gm, bm, out_msa, out_state);

    dim3 grid(L / (8 * JW), L);
    pair_kernel<<<grid, 256>>>(pair, W, b_proj, gp, bp, out_pair);
}

// round 17
// speedup vs baseline: 1.1089x; 1.0026x over previous
#include <cuda_runtime.h>
#include <cuda_fp16.h>
#include <cuda_bf16.h>
#include <cstdint>

// Problem constants (fixed shapes from setup_inputs)
#define L       1024
#define D_MSA   256
#define D_PAIR  128
#define D_STATE 32
#define FAN_IN  100            // 36 + 2*32
#define NMU     36
#define MU0     2.0f
#define DMU     (20.0f/35.0f)  // linspace(2,22,36) step
#define INV_DMU (35.0f/20.0f)
#define INV_SIG (36.0f/20.0f)  // 1/D_SIGMA, D_SIGMA = 20/36
#define NW      8              // rbf window; excluded terms < 2.4e-6

// Scratch (no cudaMalloc allowed)
__device__ float g_left [L * D_PAIR];
__device__ float g_right[L * D_PAIR];
__device__ float g_Cb   [L * 4];

// ---------------------------------------------------------------------------
// Kernel 1: per-residue prep. One block per i, 256 threads.
// ---------------------------------------------------------------------------
__global__ __launch_bounds__(256) void prep_kernel(
    const float* __restrict__ msa,
    const float* __restrict__ xyz,
    const float* __restrict__ state,
    const float* __restrict__ W,
    const float* __restrict__ gs, const float* __restrict__ bs,
    const float* __restrict__ gm, const float* __restrict__ bm,
    float* __restrict__ out_msa,
    float* __restrict__ out_state)
{
    const int i = blockIdx.x;
    const int t = threadIdx.x;

    __shared__ float s_part[16];
    __shared__ float s_stats[2];
    __shared__ float s_sn[D_STATE];

    // ---- msa layernorm ----
    const float x = msa[i * D_MSA + t];
    float s = x, q = x * x;
    #pragma unroll
    for (int o = 16; o; o >>= 1) {
        s += __shfl_xor_sync(0xffffffffu, s, o);
        q += __shfl_xor_sync(0xffffffffu, q, o);
    }
    const int w = t >> 5;
    if ((t & 31) == 0) { s_part[w] = s; s_part[8 + w] = q; }
    __syncthreads();
    if (t < 32) {
        float ss = (t < 8) ? s_part[t]     : 0.0f;
        float qq = (t < 8) ? s_part[8 + t] : 0.0f;
        #pragma unroll
        for (int o = 4; o; o >>= 1) {
            ss += __shfl_xor_sync(0xffffffffu, ss, o);
            qq += __shfl_xor_sync(0xffffffffu, qq, o);
        }
        if (t == 0) {
            const float m = ss * (1.0f / D_MSA);
            const float v = qq * (1.0f / D_MSA) - m * m;
            s_stats[0] = m;
            s_stats[1] = rsqrtf(v + 1e-5f);
        }
    }
    __syncthreads();
    out_msa[i * D_MSA + t] = (x - s_stats[0]) * s_stats[1] * gm[t] + bm[t];

    // ---- state layernorm (warp 0) ----
    if (t < 32) {
        const float sx = state[i * D_STATE + t];
        float ss = sx, qq = sx * sx;
        #pragma unroll
        for (int o = 16; o; o >>= 1) {
            ss += __shfl_xor_sync(0xffffffffu, ss, o);
            qq += __shfl_xor_sync(0xffffffffu, qq, o);
        }
        const float m = ss * (1.0f / D_STATE);
        const float v = qq * (1.0f / D_STATE) - m * m;
        const float rstd = rsqrtf(v + 1e-5f);
        const float sn = (sx - m) * rstd * gs[t] + bs[t];
        s_sn[t] = sn;
        out_state[i * D_STATE + t] = sn;
    }

    // ---- Cb geometry ----
    if (t == 64) {
        const float* p = xyz + i * 9;
        const float Nx = p[0], Ny = p[1], Nz = p[2];
        const float Ax = p[3], Ay = p[4], Az = p[5];
        const float Cx = p[6], Cy = p[7], Cz = p[8];
        const float bx = Ax - Nx, by = Ay - Ny, bz = Az - Nz;
        const float cx = Cx - Ax, cy = Cy - Ay, cz = Cz - Az;
        const float ax = by * cz - bz * cy;
        const float ay = bz * cx - bx * cz;
        const float az = bx * cy - by * cx;
        g_Cb[i * 4 + 0] = -0.58273431f * ax + 0.56802827f * bx - 0.54067466f * cx + Ax;
        g_Cb[i * 4 + 1] = -0.58273431f * ay + 0.56802827f * by - 0.54067466f * cy + Ay;
        g_Cb[i * 4 + 2] = -0.58273431f * az + 0.56802827f * bz - 0.54067466f * cz + Az;
        g_Cb[i * 4 + 3] = 0.0f;
    }
    __syncthreads();

    // ---- left/right projections: W is [128][100] row-major ----
    if (t < 128) {
        const float* wr = W + t * FAN_IN + NMU;           // W_l row
        float acc = 0.0f;
        #pragma unroll
        for (int k = 0; k < D_STATE; ++k) acc += s_sn[k] * wr[k];
        g_left[i * D_PAIR + t] = acc;
    } else {
        const int p = t - 128;
        const float* wr = W + p * FAN_IN + NMU + D_STATE; // W_r row
        float acc = 0.0f;
        #pragma unroll
        for (int k = 0; k < D_STATE; ++k) acc += s_sn[k] * wr[k];
        g_right[i * D_PAIR + p] = acc;
    }
}

// ---------------------------------------------------------------------------
// Kernel 2: pair_out[i,j,:]. grid = (16, 1024), 256 threads = 8 warps.
// Each warp iterates over JW=8 j's, 2 at a time: lanes 0-15 handle j0,
// lanes 16-31 handle j1. A lane owns 8 channels: [ca..ca+3] and [ca+64..+67].
// W_d in shared as fp16, repacked so each lane's 8 channels are one LDS.128.
// ---------------------------------------------------------------------------
#define JW 8

__global__ __launch_bounds__(256, 4) void pair_kernel(
    const float* __restrict__ pair,
    const float* __restrict__ W,
    const float* __restrict__ b_proj,
    const float* __restrict__ gp_g, const float* __restrict__ bp_g,
    float* __restrict__ out_pair)
{
    // s_wd[k][l16*8 + s]: s=0..3 -> channel l16*4+s ; s=4..7 -> channel l16*4+64+(s-4)
    __shared__ __half s_wd[NMU * D_PAIR];   // 9 KB
    __shared__ float  s_base[D_PAIR];       // left[i] + b_proj + b_pair

    const int i = blockIdx.y;
    const int t = threadIdx.x;

    for (int idx = t; idx < NMU * D_PAIR; idx += 256) {
        const int k   = idx >> 7;
        const int r   = idx & 127;
        const int g16 = r >> 3;
        const int sub = r & 7;
        const int p   = g16 * 4 + (sub & 3) + ((sub & 4) << 4);  // +64 if sub>=4
        s_wd[idx] = __float2half(W[p * FAN_IN + k]);
    }
    if (t < D_PAIR) s_base[t] = g_left[i * D_PAIR + t] + b_proj[t] + bp_g[t];
    __syncthreads();

    const int lane = t & 31;
    const int warp = t >> 5;
    const int hf   = lane >> 4;      // which j of the pair this lane serves
    const int l16  = lane & 15;
    const int ca   = l16 * 4;        // channels ca..ca+3 and ca+64..ca+67

    // per-channel constants (registers)
    const float4 ga = *(const float4*)(gp_g + ca);
    const float4 gb = *(const float4*)(gp_g + ca + 64);
    const float4 basea = *(const float4*)(s_base + ca);
    const float4 baseb = *(const float4*)(s_base + ca + 64);
    const float4 cbi = *(const float4*)(g_Cb + i * 4);

    const int jbase = blockIdx.x * (8 * JW) + warp * JW;

    for (int jj = 0; jj < JW; jj += 2) {
        const int j = jbase + jj + hf;
        const size_t row = ((size_t)i * L + j) * D_PAIR;

        // pair row slice
        const float4 pa = *(const float4*)(pair + row + ca);
        const float4 pb = *(const float4*)(pair + row + ca + 64);

        float s = (pa.x + pa.y) + (pa.z + pa.w) + (pb.x + pb.y) + (pb.z + pb.w);
        float q = pa.x * pa.x + pa.y * pa.y + pa.z * pa.z + pa.w * pa.w
                + pb.x * pb.x + pb.y * pb.y + pb.z * pb.z + pb.w * pb.w;
        #pragma unroll
        for (int o = 8; o; o >>= 1) {     // 16-lane butterfly, stays in half
            s += __shfl_xor_sync(0xffffffffu, s, o);
            q += __shfl_xor_sync(0xffffffffu, q, o);
        }
        const float mean = s * (1.0f / D_PAIR);
        const float var  = q * (1.0f / D_PAIR) - mean * mean;
        const float rstd = rsqrtf(var + 1e-5f);

        // distance + windowed rbf (one j per half-warp)
        const float4 cbj = *(const float4*)(g_Cb + j * 4);
        const float dx = cbi.x - cbj.x, dy = cbi.y - cbj.y, dz = cbi.z - cbj.z;
        const float D = sqrtf(fmaxf(dx * dx + dy * dy + dz * dz, 1e-12f));
        int k0 = (int)floorf((D - MU0) * INV_DMU + 0.5f) - (NW / 2);
        k0 = max(0, min(NMU - NW, k0));
        float myr = 0.0f;
        if (l16 < NW) {
            const float mu = MU0 + (float)(k0 + l16) * DMU;
            const float xx = (D - mu) * INV_SIG;
            myr = __expf(-xx * xx);
        }

        // acc = base + right[j] + sum_k r_k * W_d[:,k]
        const float4 ra = *(const float4*)(g_right + (size_t)j * D_PAIR + ca);
        const float4 rb = *(const float4*)(g_right + (size_t)j * D_PAIR + ca + 64);
        float4 acc_a, acc_b;
        acc_a.x = basea.x + ra.x; acc_a.y = basea.y + ra.y;
        acc_a.z = basea.z + ra.z; acc_a.w = basea.w + ra.w;
        acc_b.x = baseb.x + rb.x; acc_b.y = baseb.y + rb.y;
        acc_b.z = baseb.z + rb.z; acc_b.w = baseb.w + rb.w;

        const __half* wbase = s_wd + k0 * D_PAIR + l16 * 8;
        #pragma unroll
        for (int k = 0; k < NW; ++k) {
            const float r = __shfl_sync(0xffffffffu, myr, k, 16); // per-half source
            const uint4 wv = *(const uint4*)(wbase + k * D_PAIR); // 8 halfs, one LDS.128
            const float2 wa0 = __half22float2(*(const __half2*)&wv.x);
            const float2 wa1 = __half22float2(*(const __half2*)&wv.y);
            const float2 wb0 = __half22float2(*(const __half2*)&wv.z);
            const float2 wb1 = __half22float2(*(const __half2*)&wv.w);
            acc_a.x += r * wa0.x; acc_a.y += r * wa0.y;
            acc_a.z += r * wa1.x; acc_a.w += r * wa1.y;
            acc_b.x += r * wb0.x; acc_b.y += r * wb0.y;
            acc_b.z += r * wb1.x; acc_b.w += r * wb1.y;
        }

        // + layernorm(pair)  (b_pair already folded into base)
        float4 oa, ob;
        oa.x = acc_a.x + (pa.x - mean) * rstd * ga.x;
        oa.y = acc_a.y + (pa.y - mean) * rstd * ga.y;
        oa.z = acc_a.z + (pa.z - mean) * rstd * ga.z;
        oa.w = acc_a.w + (pa.w - mean) * rstd * ga.w;
        ob.x = acc_b.x + (pb.x - mean) * rstd * gb.x;
        ob.y = acc_b.y + (pb.y - mean) * rstd * gb.y;
        ob.z = acc_b.z + (pb.z - mean) * rstd * gb.z;
        ob.w = acc_b.w + (pb.w - mean) * rstd * gb.w;
        *(float4*)(out_pair + row + ca)      = oa;
        *(float4*)(out_pair + row + ca + 64) = ob;
    }
}

// ---------------------------------------------------------------------------
// Launch. Inputs (metadata order):
//  0 seq(i32,unused) 1 msa 2 pair 3 xyz 4 state 5 W 6 b_proj
//  7 g_state 8 b_state 9 g_pair 10 b_pair 11 g_msa 12 b_msa
// Output: concat(msa_out, pair_out, state_n) f32
// ---------------------------------------------------------------------------
extern "C" void kernel_launch(void* const* d_in, const int* in_sizes, int n_in,
                              void* d_out, int out_size)
{
    (void)in_sizes; (void)n_in; (void)out_size;
    const float* msa    = (const float*)d_in[1];
    const float* pair   = (const float*)d_in[2];
    const float* xyz    = (const float*)d_in[3];
    const float* state  = (const float*)d_in[4];
    const float* W      = (const float*)d_in[5];
    const float* b_proj = (const float*)d_in[6];
    const float* gs     = (const float*)d_in[7];
    const float* bs     = (const float*)d_in[8];
    const float* gp     = (const float*)d_in[9];
    const float* bp     = (const float*)d_in[10];
    const float* gm     = (const float*)d_in[11];
    const float* bm     = (const float*)d_in[12];

    float* out       = (float*)d_out;
    float* out_msa   = out;
    float* out_pair  = out + (size_t)L * D_MSA;
    float* out_state = out_pair + (size_t)L * L * D_PAIR;

    prep_kernel<<<L, 256>>>(msa, xyz, state, W, gs, bs, gm, bm, out_msa, out_state);

    dim3 grid(L / (8 * JW), L);
    pair_kernel<<<grid, 256>>>(pair, W, b_proj, gp, bp, out_pair);
}